// round 1
// baseline (speedup 1.0000x reference)
#include <cuda_runtime.h>
#include <cuda_bf16.h>

// DilatedAttention: b=2,h=16,s=8192,d=64; groups (w,r) = (4,1),(8,2),(16,4).
// All groups have L=4 keys and live inside aligned 16-position superblocks.
// One 128-thread block per superblock; pure streaming pass over q,k,v -> out.

#define D        64
#define SBP      16          // positions per superblock
#define STRIDE   65          // smem row stride (floats) -> bank(r,c)=(r+c)%32
#define TPB      128

__global__ __launch_bounds__(TPB, 16)
void dilated_attn_kernel(const float* __restrict__ q,
                         const float* __restrict__ k,
                         const float* __restrict__ v,
                         const float* __restrict__ alpha,
                         float* __restrict__ out)
{
    __shared__ float qs[SBP * STRIDE];   // reused as out-tile in AV phase
    __shared__ float ks[SBP * STRIDE];
    __shared__ float vs[SBP * STRIDE];
    __shared__ float ps[128];            // softmax probs: g0 [0,64), g1 [64,96), g2 [96,112)
    __shared__ float wmix[3];

    const int tid  = threadIdx.x;
    const size_t base = (size_t)blockIdx.x * (SBP * D);   // float offset of this superblock

    // ---- mixing weights: softmax(alpha) over 3 groups ----
    if (tid == 0) {
        float a0 = alpha[0], a1 = alpha[1], a2 = alpha[2];
        float m  = fmaxf(a0, fmaxf(a1, a2));
        float e0 = __expf(a0 - m), e1 = __expf(a1 - m), e2 = __expf(a2 - m);
        float inv = 1.0f / (e0 + e1 + e2);
        wmix[0] = e0 * inv; wmix[1] = e1 * inv; wmix[2] = e2 * inv;
    }

    // ---- load q,k,v tiles (16x64 each), float4 coalesced -> padded smem ----
    {
        const float4* q4 = (const float4*)(q + base);
        const float4* k4 = (const float4*)(k + base);
        const float4* v4 = (const float4*)(v + base);
        #pragma unroll
        for (int i = 0; i < 2; i++) {
            int idx = tid + i * TPB;          // float4 index 0..255
            int r   = idx >> 4;               // row 0..15
            int c   = (idx & 15) << 2;        // col 0..60
            float4 a = q4[idx];
            qs[r * STRIDE + c + 0] = a.x; qs[r * STRIDE + c + 1] = a.y;
            qs[r * STRIDE + c + 2] = a.z; qs[r * STRIDE + c + 3] = a.w;
            float4 b = k4[idx];
            ks[r * STRIDE + c + 0] = b.x; ks[r * STRIDE + c + 1] = b.y;
            ks[r * STRIDE + c + 2] = b.z; ks[r * STRIDE + c + 3] = b.w;
            float4 cc = v4[idx];
            vs[r * STRIDE + c + 0] = cc.x; vs[r * STRIDE + c + 1] = cc.y;
            vs[r * STRIDE + c + 2] = cc.z; vs[r * STRIDE + c + 3] = cc.w;
        }
    }
    __syncthreads();

    // ---- dot phase: 112 dots (one per thread), quad softmax over 4 keys ----
    {
        int qrow = 0, krow = 0, pslot = 0;
        const int warp = tid >> 5;
        if (warp < 2) {                      // group0: positions 0..15, keys in own 4-window
            int inst = tid >> 2;             // 0..15 == position
            int kj   = tid & 3;
            qrow  = inst;
            krow  = (inst & ~3) | kj;
            pslot = tid;
        } else if (warp == 2) {              // group1: 8 instances (even positions)
            int l    = tid - 64;
            int inst = l >> 2, kj = l & 3;
            int win  = inst >> 2, qi = inst & 3;
            qrow  = win * 8 + qi * 2;
            krow  = win * 8 + kj * 2;
            pslot = 64 + l;
        } else {                             // group2: 4 instances {0,4,8,12}; tid>=112 dummy
            int l    = tid - 96;
            int inst = (l >> 2) & 3, kj = l & 3;
            qrow  = inst * 4;
            krow  = kj * 4;
            pslot = 96 + l;
        }

        float acc = 0.0f;
        #pragma unroll
        for (int dm = 0; dm < D; dm++)
            acc = fmaf(qs[qrow * STRIDE + dm], ks[krow * STRIDE + dm], acc);
        acc *= 0.125f;                        // d^-0.5 = 1/8

        // softmax across the 4 keys (quad of lanes)
        float m = acc;
        m = fmaxf(m, __shfl_xor_sync(0xFFFFFFFFu, m, 1));
        m = fmaxf(m, __shfl_xor_sync(0xFFFFFFFFu, m, 2));
        float e = __expf(acc - m);
        float s = e;
        s += __shfl_xor_sync(0xFFFFFFFFu, s, 1);
        s += __shfl_xor_sync(0xFFFFFFFFu, s, 2);
        if (tid < 112) ps[pslot] = e / s;
    }
    __syncthreads();

    // ---- AV phase: accumulate weighted group outputs into out-tile (aliases qs) ----
    float* os = qs;                          // q tile no longer needed
    const int dcol = tid & 63;
    const int i2   = tid >> 6;               // 0 or 1: two instances per iteration

    // group0: 16 instances, overwrite (covers every position -> no zero-init needed)
    {
        const float W0 = wmix[0];
        #pragma unroll
        for (int it = 0; it < 8; it++) {
            int p  = it * 2 + i2;            // position 0..15
            int kb = p & ~3;
            float o = 0.0f;
            #pragma unroll
            for (int j = 0; j < 4; j++)
                o = fmaf(ps[p * 4 + j], vs[(kb + j) * STRIDE + dcol], o);
            os[p * STRIDE + dcol] = W0 * o;
        }
    }
    __syncthreads();

    // group1: 8 instances at even positions, accumulate
    {
        const float W1 = wmix[1];
        #pragma unroll
        for (int it = 0; it < 4; it++) {
            int inst = it * 2 + i2;          // 0..7
            int win  = inst >> 2, qi = inst & 3;
            int p    = win * 8 + qi * 2;
            float o  = 0.0f;
            #pragma unroll
            for (int j = 0; j < 4; j++)
                o = fmaf(ps[64 + inst * 4 + j], vs[(win * 8 + 2 * j) * STRIDE + dcol], o);
            os[p * STRIDE + dcol] += W1 * o;
        }
    }
    __syncthreads();

    // group2: 4 instances at positions {0,4,8,12}, accumulate
    {
        const float W2 = wmix[2];
        #pragma unroll
        for (int it = 0; it < 2; it++) {
            int inst = it * 2 + i2;          // 0..3
            int p    = inst * 4;
            float o  = 0.0f;
            #pragma unroll
            for (int j = 0; j < 4; j++)
                o = fmaf(ps[96 + inst * 4 + j], vs[(j * 4) * STRIDE + dcol], o);
            os[p * STRIDE + dcol] += W2 * o;
        }
    }
    __syncthreads();

    // ---- store out tile, float4 coalesced ----
    {
        float4* o4 = (float4*)(out + base);
        #pragma unroll
        for (int i = 0; i < 2; i++) {
            int idx = tid + i * TPB;
            int r   = idx >> 4;
            int c   = (idx & 15) << 2;
            float4 a;
            a.x = os[r * STRIDE + c + 0];
            a.y = os[r * STRIDE + c + 1];
            a.z = os[r * STRIDE + c + 2];
            a.w = os[r * STRIDE + c + 3];
            o4[idx] = a;
        }
    }
}

extern "C" void kernel_launch(void* const* d_in, const int* in_sizes, int n_in,
                              void* d_out, int out_size)
{
    const float* q     = (const float*)d_in[0];
    const float* k     = (const float*)d_in[1];
    const float* v     = (const float*)d_in[2];
    const float* alpha = (const float*)d_in[3];
    float* out         = (float*)d_out;

    int n_superblocks = in_sizes[0] / (SBP * D);   // 2*16*8192/16 = 16384
    dilated_attn_kernel<<<n_superblocks, TPB>>>(q, k, v, alpha, out);
}

// round 2
// speedup vs baseline: 1.6598x; 1.6598x over previous
#include <cuda_runtime.h>
#include <cuda_bf16.h>

// DilatedAttention: b=2,h=16,s=8192,d=64; groups (w,r)=(4,1),(8,2),(16,4).
// Every group's instance lives inside an aligned 16-position superblock.
// One 128-thread block per superblock. All smem accesses float4-vectorized
// with a per-row swizzle g(r)=(r+(r>>3))&7 making all four row-access sets
// ({0..7},{8..15},evens,{0,4,8,12}) bank-conflict-free.

#define TPB 128

__device__ __forceinline__ int rswz(int r)   { return (r + (r >> 3)) & 7; }
__device__ __forceinline__ int sl(int c4, int g) { return (c4 & 8) | ((c4 + g) & 7); }

__device__ __forceinline__ void cpasync16(void* smem_dst, const void* gmem_src) {
    unsigned s = (unsigned)__cvta_generic_to_shared(smem_dst);
    asm volatile("cp.async.cg.shared.global [%0], [%1], 16;\n" :: "r"(s), "l"(gmem_src));
}

__global__ __launch_bounds__(TPB, 12)
void dilated_attn_kernel(const float* __restrict__ q,
                         const float* __restrict__ k,
                         const float* __restrict__ v,
                         const float* __restrict__ alpha,
                         float* __restrict__ out)
{
    __shared__ float4 qs[16 * 16];
    __shared__ float4 ks[16 * 16];
    __shared__ float4 vs[16 * 16];
    __shared__ float  ps[128];     // probs: g0 [0,64), g1 [64,96), g2 [96,112)

    const int tid = threadIdx.x;
    const size_t base = (size_t)blockIdx.x * 1024;   // floats

    // ---- mixing weights softmax(alpha), per-thread in registers ----
    float a0 = __ldg(alpha + 0), a1 = __ldg(alpha + 1), a2 = __ldg(alpha + 2);
    float am = fmaxf(a0, fmaxf(a1, a2));
    float e0 = __expf(a0 - am), e1 = __expf(a1 - am), e2 = __expf(a2 - am);
    float wi = 1.0f / (e0 + e1 + e2);
    const float W0 = e0 * wi, W1 = e1 * wi, W2 = e2 * wi;

    // ---- stage q,k,v tiles (16x64) into swizzled smem via cp.async ----
    {
        const float4* q4 = (const float4*)(q + base);
        const float4* k4 = (const float4*)(k + base);
        const float4* v4 = (const float4*)(v + base);
        #pragma unroll
        for (int i = 0; i < 2; i++) {
            int idx = tid + i * TPB;               // 0..255
            int r   = idx >> 4;                    // row 0..15
            int c4  = idx & 15;                    // float4 col
            int d   = r * 16 + sl(c4, rswz(r));
            cpasync16(&qs[d], &q4[idx]);
            cpasync16(&ks[d], &k4[idx]);
            cpasync16(&vs[d], &v4[idx]);
        }
        asm volatile("cp.async.commit_group;\n");
        asm volatile("cp.async.wait_group 0;\n");
    }
    __syncthreads();

    // ---- dot phase: 112 dots, one per thread; quad softmax over 4 keys ----
    {
        int qrow, krow, pidx;
        const int warp = tid >> 5;
        if (warp < 2) {                      // g0: 16 instances x 4 keys
            int inst = tid >> 2, kj = tid & 3;
            qrow = inst;
            krow = (inst & ~3) | kj;
            pidx = tid;
        } else if (warp == 2) {              // g1: 8 instances (even positions)
            int l = tid - 64;
            int inst = l >> 2, kj = l & 3;
            int win = inst >> 2, qi = inst & 3;
            qrow = win * 8 + qi * 2;
            krow = win * 8 + kj * 2;
            pidx = 64 + l;
        } else {                             // g2: 4 instances; tid>=112 dummy
            int l = tid - 96;
            int inst = (l >> 2) & 3, kj = l & 3;
            qrow = inst * 4;
            krow = kj * 4;
            pidx = 96 + l;
        }

        const float4* qr = qs + qrow * 16;
        const float4* kr = ks + krow * 16;
        const int gq = rswz(qrow), gk = rswz(krow);

        float acc = 0.0f;
        #pragma unroll
        for (int c = 0; c < 16; c++) {
            float4 a = qr[sl(c, gq)];
            float4 b = kr[sl(c, gk)];
            acc = fmaf(a.x, b.x, acc);
            acc = fmaf(a.y, b.y, acc);
            acc = fmaf(a.z, b.z, acc);
            acc = fmaf(a.w, b.w, acc);
        }
        acc *= 0.125f;                       // d^-0.5 = 1/8

        float m = acc;
        m = fmaxf(m, __shfl_xor_sync(0xFFFFFFFFu, m, 1));
        m = fmaxf(m, __shfl_xor_sync(0xFFFFFFFFu, m, 2));
        float e = __expf(acc - m);
        float s = e;
        s += __shfl_xor_sync(0xFFFFFFFFu, s, 1);
        s += __shfl_xor_sync(0xFFFFFFFFu, s, 2);
        if (tid < 112) ps[pidx] = e / s;
    }
    __syncthreads();

    // ---- AV phase: register accumulation, direct GMEM store ----
    // thread = (c4 = tid&15, s = tid>>4); positions p0 = 2s (even), p1 = 2s+1.
    {
        const int c4 = tid & 15;
        const int s  = tid >> 4;             // 0..7
        const int p0 = 2 * s, p1 = p0 + 1;

        float ax0 = 0, ay0 = 0, az0 = 0, aw0 = 0;   // output p0
        float ax1 = 0, ay1 = 0, az1 = 0, aw1 = 0;   // output p1

        // group0: window w = p0>>2, rows w*4+j, shared by p0 and p1
        {
            const int w = p0 >> 2;
            float sx0=0, sy0=0, sz0=0, sw0=0, sx1=0, sy1=0, sz1=0, sw1=0;
            #pragma unroll
            for (int j = 0; j < 4; j++) {
                int row = w * 4 + j;
                float4 vv = vs[row * 16 + sl(c4, rswz(row))];
                float w0 = ps[p0 * 4 + j];
                float w1 = ps[p1 * 4 + j];
                sx0 = fmaf(w0, vv.x, sx0); sy0 = fmaf(w0, vv.y, sy0);
                sz0 = fmaf(w0, vv.z, sz0); sw0 = fmaf(w0, vv.w, sw0);
                sx1 = fmaf(w1, vv.x, sx1); sy1 = fmaf(w1, vv.y, sy1);
                sz1 = fmaf(w1, vv.z, sz1); sw1 = fmaf(w1, vv.w, sw1);
            }
            ax0 = W0 * sx0; ay0 = W0 * sy0; az0 = W0 * sz0; aw0 = W0 * sw0;
            ax1 = W0 * sx1; ay1 = W0 * sy1; az1 = W0 * sz1; aw1 = W0 * sw1;
        }

        // group1: p0 is always even -> instance inst1, rows win*8 + 2j
        {
            const int win  = p0 >> 3;
            const int inst = win * 4 + ((p0 >> 1) & 3);
            float sx=0, sy=0, sz=0, sw=0;
            #pragma unroll
            for (int j = 0; j < 4; j++) {
                int row = win * 8 + 2 * j;
                float4 vv = vs[row * 16 + sl(c4, rswz(row))];
                float wj = ps[64 + inst * 4 + j];
                sx = fmaf(wj, vv.x, sx); sy = fmaf(wj, vv.y, sy);
                sz = fmaf(wj, vv.z, sz); sw = fmaf(wj, vv.w, sw);
            }
            ax0 = fmaf(W1, sx, ax0); ay0 = fmaf(W1, sy, ay0);
            az0 = fmaf(W1, sz, az0); aw0 = fmaf(W1, sw, aw0);
        }

        // group2: only positions p ≡ 0 (mod 4), i.e. s even -> p0 = 4*(s/2)
        if ((p0 & 3) == 0) {
            const int inst = p0 >> 2;
            float sx=0, sy=0, sz=0, sw=0;
            #pragma unroll
            for (int j = 0; j < 4; j++) {
                int row = 4 * j;
                float4 vv = vs[row * 16 + sl(c4, rswz(row))];
                float wj = ps[96 + inst * 4 + j];
                sx = fmaf(wj, vv.x, sx); sy = fmaf(wj, vv.y, sy);
                sz = fmaf(wj, vv.z, sz); sw = fmaf(wj, vv.w, sw);
            }
            ax0 = fmaf(W2, sx, ax0); ay0 = fmaf(W2, sy, ay0);
            az0 = fmaf(W2, sz, az0); aw0 = fmaf(W2, sw, aw0);
        }

        float4* o4 = (float4*)(out + base);
        float4 r0; r0.x = ax0; r0.y = ay0; r0.z = az0; r0.w = aw0;
        float4 r1; r1.x = ax1; r1.y = ay1; r1.z = az1; r1.w = aw1;
        o4[p0 * 16 + c4] = r0;
        o4[p1 * 16 + c4] = r1;
    }
}

extern "C" void kernel_launch(void* const* d_in, const int* in_sizes, int n_in,
                              void* d_out, int out_size)
{
    const float* q     = (const float*)d_in[0];
    const float* k     = (const float*)d_in[1];
    const float* v     = (const float*)d_in[2];
    const float* alpha = (const float*)d_in[3];
    float* out         = (float*)d_out;

    int n_superblocks = in_sizes[0] / 1024;   // 16384
    dilated_attn_kernel<<<n_superblocks, TPB>>>(q, k, v, alpha, out);
}

// round 3
// speedup vs baseline: 1.6760x; 1.0098x over previous
#include <cuda_runtime.h>
#include <cuda_bf16.h>

// DilatedAttention: b=2,h=16,s=8192,d=64; groups (w,r)=(4,1),(8,2),(16,4).
// One 128-thread block per 16-position superblock.
// XOR smem swizzle g(r)=(r^(r>>3))&7 is bank-conflict-free for all row sets
// used here: {0..7},{8..15},{0,2,..,14},{0,4,8,12}, and any single row.

#define TPB 128

__device__ __forceinline__ int rswz(int r) { return (r ^ (r >> 3)) & 7; }

__device__ __forceinline__ void cpasync16(void* smem_dst, const void* gmem_src) {
    unsigned s = (unsigned)__cvta_generic_to_shared(smem_dst);
    asm volatile("cp.async.cg.shared.global [%0], [%1], 16;\n" :: "r"(s), "l"(gmem_src));
}

__global__ __launch_bounds__(TPB, 14)
void dilated_attn_kernel(const float* __restrict__ q,
                         const float* __restrict__ k,
                         const float* __restrict__ v,
                         const float* __restrict__ alpha,
                         float* __restrict__ out)
{
    __shared__ float4 qs[16 * 16];
    __shared__ float4 ks[16 * 16];
    __shared__ float4 vs[16 * 16];
    __shared__ float4 ps[32];      // probs per instance: g0 [0,16), g1 [16,24), g2 [24,28)
    __shared__ float  wmix[3];

    const int tid = threadIdx.x;
    const size_t base = (size_t)blockIdx.x * 1024;   // floats

    // ---- stage q,k,v tiles (16x64) into XOR-swizzled smem via cp.async ----
    {
        const float4* q4 = (const float4*)(q + base);
        const float4* k4 = (const float4*)(k + base);
        const float4* v4 = (const float4*)(v + base);
        #pragma unroll
        for (int i = 0; i < 2; i++) {
            int idx = tid + i * TPB;               // 0..255
            int r   = idx >> 4;                    // row 0..15
            int c4  = idx & 15;
            int d   = r * 16 + (c4 ^ rswz(r));
            cpasync16(&qs[d], &q4[idx]);
            cpasync16(&ks[d], &k4[idx]);
            cpasync16(&vs[d], &v4[idx]);
        }
        asm volatile("cp.async.commit_group;\n");
    }

    // ---- mixing weights softmax(alpha): one thread, into smem ----
    if (tid == 0) {
        float a0 = __ldg(alpha + 0), a1 = __ldg(alpha + 1), a2 = __ldg(alpha + 2);
        float am = fmaxf(a0, fmaxf(a1, a2));
        float e0 = __expf(a0 - am), e1 = __expf(a1 - am), e2 = __expf(a2 - am);
        float wi = 1.0f / (e0 + e1 + e2);
        wmix[0] = e0 * wi; wmix[1] = e1 * wi; wmix[2] = e2 * wi;
    }

    asm volatile("cp.async.wait_group 0;\n");
    __syncthreads();

    // ---- dot phase: 112 dots, one per thread; quad softmax over 4 keys ----
    {
        int qrow, krow, pinst;
        const int warp = tid >> 5;
        const int kj   = tid & 3;
        if (warp < 2) {                      // g0: 16 instances x 4 keys
            int inst = tid >> 2;
            qrow  = inst;
            krow  = (inst & ~3) | kj;
            pinst = inst;                    // ps slot 0..15
        } else if (warp == 2) {              // g1: 8 instances (even positions)
            int l = tid - 64;
            int inst = l >> 2;
            int win = inst >> 2, qi = inst & 3;
            qrow  = win * 8 + qi * 2;
            krow  = win * 8 + kj * 2;
            pinst = 16 + inst;
        } else {                             // g2: 4 instances; lanes>=16 dummy
            int l = tid - 96;
            int inst = (l >> 2) & 3;
            qrow  = inst * 4;
            krow  = kj * 4;
            pinst = 24 + inst;
        }

        const float4* qr = qs + qrow * 16;
        const float4* kr = ks + krow * 16;
        const int gq = rswz(qrow), gk = rswz(krow);

        float acc = 0.0f;
        #pragma unroll
        for (int c = 0; c < 16; c++) {
            float4 a = qr[c ^ gq];
            float4 b = kr[c ^ gk];
            acc = fmaf(a.x, b.x, acc);
            acc = fmaf(a.y, b.y, acc);
            acc = fmaf(a.z, b.z, acc);
            acc = fmaf(a.w, b.w, acc);
        }
        acc *= 0.125f;                       // d^-0.5 = 1/8

        float m = acc;
        m = fmaxf(m, __shfl_xor_sync(0xFFFFFFFFu, m, 1));
        m = fmaxf(m, __shfl_xor_sync(0xFFFFFFFFu, m, 2));
        float e = __expf(acc - m);
        float s = e;
        s += __shfl_xor_sync(0xFFFFFFFFu, s, 1);
        s += __shfl_xor_sync(0xFFFFFFFFu, s, 2);
        // pack the 4 probs of this instance into one float4 (lane kj==0 writes)
        float p1 = __shfl_sync(0xFFFFFFFFu, e / s, (tid & 31) | 1);
        float p2 = __shfl_sync(0xFFFFFFFFu, e / s, (tid & 31) | 2);
        float p3 = __shfl_sync(0xFFFFFFFFu, e / s, (tid & 31) | 3);
        if (kj == 0 && tid < 112) {
            float4 pv; pv.x = e / s; pv.y = p1; pv.z = p2; pv.w = p3;
            ps[pinst] = pv;
        }
    }
    __syncthreads();

    // ---- AV phase: register accumulation, direct GMEM store ----
    // thread = (c4 = tid&15, s = tid>>4); positions p0 = 2s (even), p1 = 2s+1.
    {
        const int c4 = tid & 15;
        const int s  = tid >> 4;             // 0..7
        const int p0 = 2 * s, p1 = p0 + 1;
        const float W0 = wmix[0], W1 = wmix[1], W2 = wmix[2];

        float ax0, ay0, az0, aw0, ax1, ay1, az1, aw1;

        // group0: window w = p0>>2; rows w*4+j shared by p0 and p1
        {
            const int w = p0 >> 2;
            float4 pa = ps[p0];              // probs for instance p0
            float4 pb = ps[p1];
            float4 v0 = vs[(w*4+0) * 16 + (c4 ^ rswz(w*4+0))];
            float4 v1 = vs[(w*4+1) * 16 + (c4 ^ rswz(w*4+1))];
            float4 v2 = vs[(w*4+2) * 16 + (c4 ^ rswz(w*4+2))];
            float4 v3 = vs[(w*4+3) * 16 + (c4 ^ rswz(w*4+3))];
            float sx0, sy0, sz0, sw0, sx1, sy1, sz1, sw1;
            sx0 = pa.x*v0.x; sy0 = pa.x*v0.y; sz0 = pa.x*v0.z; sw0 = pa.x*v0.w;
            sx1 = pb.x*v0.x; sy1 = pb.x*v0.y; sz1 = pb.x*v0.z; sw1 = pb.x*v0.w;
            sx0 = fmaf(pa.y, v1.x, sx0); sy0 = fmaf(pa.y, v1.y, sy0);
            sz0 = fmaf(pa.y, v1.z, sz0); sw0 = fmaf(pa.y, v1.w, sw0);
            sx1 = fmaf(pb.y, v1.x, sx1); sy1 = fmaf(pb.y, v1.y, sy1);
            sz1 = fmaf(pb.y, v1.z, sz1); sw1 = fmaf(pb.y, v1.w, sw1);
            sx0 = fmaf(pa.z, v2.x, sx0); sy0 = fmaf(pa.z, v2.y, sy0);
            sz0 = fmaf(pa.z, v2.z, sz0); sw0 = fmaf(pa.z, v2.w, sw0);
            sx1 = fmaf(pb.z, v2.x, sx1); sy1 = fmaf(pb.z, v2.y, sy1);
            sz1 = fmaf(pb.z, v2.z, sz1); sw1 = fmaf(pb.z, v2.w, sw1);
            sx0 = fmaf(pa.w, v3.x, sx0); sy0 = fmaf(pa.w, v3.y, sy0);
            sz0 = fmaf(pa.w, v3.z, sz0); sw0 = fmaf(pa.w, v3.w, sw0);
            sx1 = fmaf(pb.w, v3.x, sx1); sy1 = fmaf(pb.w, v3.y, sy1);
            sz1 = fmaf(pb.w, v3.z, sz1); sw1 = fmaf(pb.w, v3.w, sw1);
            ax0 = W0*sx0; ay0 = W0*sy0; az0 = W0*sz0; aw0 = W0*sw0;
            ax1 = W0*sx1; ay1 = W0*sy1; az1 = W0*sz1; aw1 = W0*sw1;
        }

        // group1: p0 even -> instance; rows win*8 + 2j
        {
            const int win  = p0 >> 3;
            const int inst = win * 4 + ((p0 >> 1) & 3);
            float4 pa = ps[16 + inst];
            float sx = 0, sy = 0, sz = 0, sw = 0;
            #pragma unroll
            for (int j = 0; j < 4; j++) {
                int row = win * 8 + 2 * j;
                float4 vv = vs[row * 16 + (c4 ^ rswz(row))];
                float wj = (j == 0) ? pa.x : (j == 1) ? pa.y : (j == 2) ? pa.z : pa.w;
                sx = fmaf(wj, vv.x, sx); sy = fmaf(wj, vv.y, sy);
                sz = fmaf(wj, vv.z, sz); sw = fmaf(wj, vv.w, sw);
            }
            ax0 = fmaf(W1, sx, ax0); ay0 = fmaf(W1, sy, ay0);
            az0 = fmaf(W1, sz, az0); aw0 = fmaf(W1, sw, aw0);
        }

        // group2: only positions p ≡ 0 (mod 4)
        if ((p0 & 3) == 0) {
            const int inst = p0 >> 2;
            float4 pa = ps[24 + inst];
            float sx = 0, sy = 0, sz = 0, sw = 0;
            #pragma unroll
            for (int j = 0; j < 4; j++) {
                int row = 4 * j;
                float4 vv = vs[row * 16 + (c4 ^ rswz(row))];
                float wj = (j == 0) ? pa.x : (j == 1) ? pa.y : (j == 2) ? pa.z : pa.w;
                sx = fmaf(wj, vv.x, sx); sy = fmaf(wj, vv.y, sy);
                sz = fmaf(wj, vv.z, sz); sw = fmaf(wj, vv.w, sw);
            }
            ax0 = fmaf(W2, sx, ax0); ay0 = fmaf(W2, sy, ay0);
            az0 = fmaf(W2, sz, az0); aw0 = fmaf(W2, sw, aw0);
        }

        float4* o4 = (float4*)(out + base);
        float4 r0; r0.x = ax0; r0.y = ay0; r0.z = az0; r0.w = aw0;
        float4 r1; r1.x = ax1; r1.y = ay1; r1.z = az1; r1.w = aw1;
        __stcs(&o4[p0 * 16 + c4], r0);
        __stcs(&o4[p1 * 16 + c4], r1);
    }
}

extern "C" void kernel_launch(void* const* d_in, const int* in_sizes, int n_in,
                              void* d_out, int out_size)
{
    const float* q     = (const float*)d_in[0];
    const float* k     = (const float*)d_in[1];
    const float* v     = (const float*)d_in[2];
    const float* alpha = (const float*)d_in[3];
    float* out         = (float*)d_out;

    int n_superblocks = in_sizes[0] / 1024;   // 16384
    dilated_attn_kernel<<<n_superblocks, TPB>>>(q, k, v, alpha, out);
}